// round 16
// baseline (speedup 1.0000x reference)
#include <cuda_runtime.h>
#include <cuda_bf16.h>
#include <cuda_fp16.h>
#include <cstdint>

// Problem constants (fixed by setup_inputs)
#define NMAX 100000
#define EMAX 1600000
#define FDIM 256
#define HDIM 128
#define DDIM 64
#define NB   ((NMAX + 255) / 256)   // 391 scan blocks

// ---------------- device scratch (no allocations allowed) ----------------
__device__ int   g_is32;            // 1 if edge_index is int32, 0 if int64
__device__ int   g_cnt[NMAX];
__device__ int   g_off[NMAX + 1];
__device__ int   g_pos[NMAX];
__device__ int   g_bsum[NB];
__device__ int   g_boff[NB];
__device__ int   g_srcs[EMAX];
__device__ __align__(16) float  g_dis[NMAX];
__device__ __align__(16) __half g_t[(size_t)NMAX * HDIM];   // GEMM output fp16 (t1, then t2)
__device__ __align__(16) __half g_h1[(size_t)NMAX * HDIM];  // relu(agg1+b1) in fp16 (GEMM2 A)
__device__ __align__(16) float  g_Wcat[HDIM * HDIM];        // [128,128] = [Wmu | Wvar]

// ---------------- tf32 helpers ----------------
__device__ __forceinline__ float f2tf32(float x) {
    uint32_t o;
    asm("cvt.rna.tf32.f32 %0, %1;" : "=r"(o) : "f"(x));
    return __uint_as_float(o);
}
__device__ __forceinline__ void mma_tf32(float4& d,
                                         uint32_t a0, uint32_t a1, uint32_t a2, uint32_t a3,
                                         uint32_t b0, uint32_t b1) {
    asm volatile("mma.sync.aligned.m16n8k8.row.col.f32.tf32.tf32.f32 "
                 "{%0,%1,%2,%3}, {%4,%5,%6,%7}, {%8,%9}, {%0,%1,%2,%3};\n"
                 : "+f"(d.x), "+f"(d.y), "+f"(d.z), "+f"(d.w)
                 : "r"(a0), "r"(a1), "r"(a2), "r"(a3), "r"(b0), "r"(b1));
}

// ---------------- dtype detection + zeroing ----------------
__global__ void zeros_kernel(int n) {
    int i = blockIdx.x * blockDim.x + threadIdx.x;
    if (i < n) g_cnt[i] = 0;
    if (i == 0) g_is32 = 0;
}

// Sample only the first 2048 int64-view elements. Plain store (benign race).
__global__ void detect_kernel(const void* ei, int e, int n) {
    int i = blockIdx.x * blockDim.x + threadIdx.x;
    int lim = min(e, 2048);
    if (i < lim) {
        long long v = ((const long long*)ei)[i];
        if (v < 0 || v >= (long long)n) g_is32 = 1;
    }
}

__device__ __forceinline__ int edge_src(const void* ei, int e, int i) {
    return g_is32 ? ((const int*)ei)[i] : (int)((const long long*)ei)[i];
}
__device__ __forceinline__ int edge_dst(const void* ei, int e, int i) {
    return g_is32 ? ((const int*)ei)[e + i] : (int)((const long long*)ei)[e + i];
}

// ---------------- CSR build ----------------
__global__ void count_kernel(const void* ei, int e, int n) {
    int i = blockIdx.x * blockDim.x + threadIdx.x;
    if (i < e) {
        int d = edge_dst(ei, e, i);
        d = min(max(d, 0), n - 1);
        atomicAdd(&g_cnt[d], 1);
    }
}

__global__ void dis_kernel(int n) {
    int i = blockIdx.x * blockDim.x + threadIdx.x;
    if (i < n) g_dis[i] = rsqrtf((float)(g_cnt[i] + 1));  // +1 self loop
}

// phase 1: per-block Hillis-Steele inclusive scan
__global__ void block_scan_kernel(int n) {
    __shared__ int sh[256];
    const int b = blockIdx.x, t = threadIdx.x;
    const int i = b * 256 + t;
    int v = (i < n) ? g_cnt[i] : 0;
    sh[t] = v;
    __syncthreads();
    for (int d = 1; d < 256; d <<= 1) {
        int add = (t >= d) ? sh[t - d] : 0;
        __syncthreads();
        sh[t] += add;
        __syncthreads();
    }
    if (i < n) g_off[i] = sh[t] - v;
    if (t == 255) g_bsum[b] = sh[255];
}

// phase 2: one block scans the NB block sums
__global__ void bsum_scan_kernel(int nb) {
    __shared__ int sh[512];
    const int t = threadIdx.x;
    int v = (t < nb) ? g_bsum[t] : 0;
    sh[t] = v;
    __syncthreads();
    for (int d = 1; d < 512; d <<= 1) {
        int add = (t >= d) ? sh[t - d] : 0;
        __syncthreads();
        sh[t] += add;
        __syncthreads();
    }
    if (t < nb) g_boff[t] = sh[t] - v;
}

// phase 3: add block offsets
__global__ void add_off_kernel(int n, int e) {
    int i = blockIdx.x * blockDim.x + threadIdx.x;
    if (i < n) {
        int o = g_off[i] + g_boff[i >> 8];
        g_off[i] = o;
        g_pos[i] = o;
    }
    if (i == 0) g_off[n] = e;
}

__global__ void fill_kernel(const void* ei, int e, int n) {
    int i = blockIdx.x * blockDim.x + threadIdx.x;
    if (i < e) {
        int s = edge_src(ei, e, i);
        int d = edge_dst(ei, e, i);
        s = min(max(s, 0), n - 1);
        d = min(max(d, 0), n - 1);
        int p = atomicAdd(&g_pos[d], 1);
        if (p >= 0 && p < EMAX) g_srcs[p] = s;
    }
}

__global__ void wcat_kernel(const float* __restrict__ Wmu, const float* __restrict__ Wvar) {
    int i = blockIdx.x * blockDim.x + threadIdx.x;
    if (i < HDIM * HDIM) {
        int k = i >> 7;
        int j = i & 127;
        g_Wcat[i] = (j < DDIM) ? Wmu[k * DDIM + j] : Wvar[k * DDIM + (j - DDIM)];
    }
}

// ---------------- GEMM (TF32 tensor cores, fragment-layout smem) ----------
// C[M,128] = A[M,K] @ B[K,128]; 128x128 CTA tile, BK=16, 256 threads,
// 8 warps 2m x 4n (each m64n32), mma.m16n8k8.tf32.
// Smem staged in fragment order: one LDS.128 per A-frag, LDS.64 per B-frag.
// phase 0: A = x (fp32), B = W1, K = FDIM
// phase 1: A = g_h1 (fp16), B = g_Wcat, K = HDIM
#define TBM 128
#define TBN 128
#define TBK 16

// fragment-layout scatter helpers (m,kk local to tile)
__device__ __forceinline__ void sts_a(float* asp, int m, int kk, float v) {
    int mtile = m >> 4, r = m & 15, gid = r & 7, mh = r >> 3;
    int ks = kk >> 3, tig = kk & 3, kh = (kk >> 2) & 1;
    asp[(((mtile * 2 + ks) * 32) + (gid * 4 + tig)) * 4 + kh * 2 + mh] = v;
}
__device__ __forceinline__ void sts_b(float* bsp, int kk, int nn, float v) {
    int ks = kk >> 3, tig = kk & 3, kh = (kk >> 2) & 1;
    int ntile = nn >> 3, gid = nn & 7;
    bsp[(((ntile * 2 + ks) * 32) + (gid * 4 + tig)) * 2 + kh] = v;
}

__global__ void __launch_bounds__(256, 2) gemm128_kernel(
    const float* __restrict__ Ax, const float* __restrict__ Bw,
    int M, int K, int phase)
{
    const float*  Af = (phase == 0) ? Ax : nullptr;
    const __half* Ah = (phase == 0) ? nullptr : (const __half*)g_h1;
    const float*  B  = (phase == 0) ? Bw : (const float*)g_Wcat;
    __half*       C  = g_t;

    // fragment-order staging: Asp[buf][mtile8][ks2][lane32] float4
    //                         Bsp[buf][ntile16][ks2][lane32] float2
    __shared__ __align__(16) float4 Asp[2][8][2][32];
    __shared__ __align__(16) float2 Bsp[2][16][2][32];

    const int tid  = threadIdx.x;
    const int row0 = blockIdx.x * TBM;

    // A loader: rows ar, ar+64; k cols ac..ac+3
    const int ar = tid >> 2;          // 0..63
    const int ac = (tid & 3) * 4;     // 0,4,8,12
    // B loader: k rows br, br+8; n cols bc..bc+3
    const int br = tid >> 5;          // 0..7
    const int bc = (tid & 31) * 4;    // 0..124

    const int wid  = tid >> 5;
    const int lane = tid & 31;
    const int gid  = lane >> 2;
    const int tig  = lane & 3;
    const int mb4  = (wid >> 2) * 4;      // mtile base (0 or 4)
    const int nb4  = (wid & 3) * 4;       // ntile base (0,4,8,12)
    const int mbase = (wid >> 2) * 64;
    const int nbase = (wid & 3) * 32;

    float4 acc[4][4];
    #pragma unroll
    for (int i = 0; i < 4; i++)
        #pragma unroll
        for (int j = 0; j < 4; j++) acc[i][j] = make_float4(0.f, 0.f, 0.f, 0.f);

    const int nk = K / TBK;
    const int r0 = row0 + ar;
    const int r1 = row0 + ar + 64;

    // tile loaders
    auto load_a_rows = [&](int k0, float4& a0, float4& a1) {
        a0 = make_float4(0,0,0,0); a1 = make_float4(0,0,0,0);
        if (phase == 0) {
            if (r0 < M) { float4 t = *(const float4*)&Af[(size_t)r0 * K + k0 + ac];
                          a0 = make_float4(f2tf32(t.x), f2tf32(t.y), f2tf32(t.z), f2tf32(t.w)); }
            if (r1 < M) { float4 t = *(const float4*)&Af[(size_t)r1 * K + k0 + ac];
                          a1 = make_float4(f2tf32(t.x), f2tf32(t.y), f2tf32(t.z), f2tf32(t.w)); }
        } else {
            if (r0 < M) { uint2 raw = *(const uint2*)&Ah[(size_t)r0 * K + k0 + ac];
                          float2 u = __half22float2(*(__half2*)&raw.x);
                          float2 v = __half22float2(*(__half2*)&raw.y);
                          a0 = make_float4(u.x, u.y, v.x, v.y); }   // fp16 exact in tf32
            if (r1 < M) { uint2 raw = *(const uint2*)&Ah[(size_t)r1 * K + k0 + ac];
                          float2 u = __half22float2(*(__half2*)&raw.x);
                          float2 v = __half22float2(*(__half2*)&raw.y);
                          a1 = make_float4(u.x, u.y, v.x, v.y); }
        }
    };
    auto stage_tile = [&](int buf, int k0, const float4& a0, const float4& a1,
                          const float4& b0, const float4& b1) {
        float* asp = (float*)&Asp[buf][0][0][0];
        float* bsp = (float*)&Bsp[buf][0][0][0];
        sts_a(asp, ar,      ac + 0, a0.x); sts_a(asp, ar,      ac + 1, a0.y);
        sts_a(asp, ar,      ac + 2, a0.z); sts_a(asp, ar,      ac + 3, a0.w);
        sts_a(asp, ar + 64, ac + 0, a1.x); sts_a(asp, ar + 64, ac + 1, a1.y);
        sts_a(asp, ar + 64, ac + 2, a1.z); sts_a(asp, ar + 64, ac + 3, a1.w);
        sts_b(bsp, br,     bc + 0, b0.x); sts_b(bsp, br,     bc + 1, b0.y);
        sts_b(bsp, br,     bc + 2, b0.z); sts_b(bsp, br,     bc + 3, b0.w);
        sts_b(bsp, br + 8, bc + 0, b1.x); sts_b(bsp, br + 8, bc + 1, b1.y);
        sts_b(bsp, br + 8, bc + 2, b1.z); sts_b(bsp, br + 8, bc + 3, b1.w);
    };
    auto load_b_rows = [&](int k0, float4& b0, float4& b1) {
        float4 t0 = *(const float4*)&B[(size_t)(k0 + br) * TBN + bc];
        float4 t1 = *(const float4*)&B[(size_t)(k0 + br + 8) * TBN + bc];
        b0 = make_float4(f2tf32(t0.x), f2tf32(t0.y), f2tf32(t0.z), f2tf32(t0.w));
        b1 = make_float4(f2tf32(t1.x), f2tf32(t1.y), f2tf32(t1.z), f2tf32(t1.w));
    };

    // ---- prologue: tile 0 ----
    {
        float4 a0, a1, b0, b1;
        load_a_rows(0, a0, a1);
        load_b_rows(0, b0, b1);
        stage_tile(0, 0, a0, a1, b0, b1);
    }
    __syncthreads();

    int cur = 0;
    for (int kt = 0; kt < nk; kt++) {
        const int nxt = cur ^ 1;
        const bool has_next = (kt + 1 < nk);
        float4 na0, na1, nb0, nb1;
        if (has_next) {
            const int k0 = (kt + 1) * TBK;
            load_a_rows(k0, na0, na1);
            load_b_rows(k0, nb0, nb1);
        }
        // compute: 2 ks steps, fragment loads are single wide LDS
        #pragma unroll
        for (int ks = 0; ks < 2; ks++) {
            float4 a[4];
            float2 b[4];
            #pragma unroll
            for (int mt = 0; mt < 4; mt++) a[mt] = Asp[cur][mb4 + mt][ks][lane];
            #pragma unroll
            for (int nt = 0; nt < 4; nt++) b[nt] = Bsp[cur][nb4 + nt][ks][lane];
            #pragma unroll
            for (int nt = 0; nt < 4; nt++)
                #pragma unroll
                for (int mt = 0; mt < 4; mt++)
                    mma_tf32(acc[mt][nt],
                             __float_as_uint(a[mt].x), __float_as_uint(a[mt].y),
                             __float_as_uint(a[mt].z), __float_as_uint(a[mt].w),
                             __float_as_uint(b[nt].x), __float_as_uint(b[nt].y));
        }
        if (has_next) stage_tile(nxt, 0, na0, na1, nb0, nb1);
        __syncthreads();
        cur = nxt;
    }

    // ---- epilogue: acc -> fp16 C ----
    #pragma unroll
    for (int mt = 0; mt < 4; mt++) {
        const int ra = row0 + mbase + mt * 16 + gid;
        const int rb = ra + 8;
        #pragma unroll
        for (int nt = 0; nt < 4; nt++) {
            const int c = nbase + nt * 8 + 2 * tig;
            if (ra < M) *(__half2*)&C[(size_t)ra * TBN + c] = __floats2half2_rn(acc[mt][nt].x, acc[mt][nt].y);
            if (rb < M) *(__half2*)&C[(size_t)rb * TBN + c] = __floats2half2_rn(acc[mt][nt].z, acc[mt][nt].w);
        }
    }
}

// ---------------- aggregation: warp per node, 128 features, fp16 gather ----
__device__ __forceinline__ void gather_fma(float4& acc, const __half* row, int f, float ww) {
    uint2 raw = *(const uint2*)(row + f);
    float2 m0 = __half22float2(*(__half2*)&raw.x);
    float2 m1 = __half22float2(*(__half2*)&raw.y);
    acc.x = fmaf(m0.x, ww, acc.x);
    acc.y = fmaf(m0.y, ww, acc.y);
    acc.z = fmaf(m1.x, ww, acc.z);
    acc.w = fmaf(m1.y, ww, acc.w);
}

__global__ void agg1_kernel(const float* __restrict__ b1, int n) {
    int warp = (blockIdx.x * blockDim.x + threadIdx.x) >> 5;
    int lane = threadIdx.x & 31;
    if (warp >= n) return;
    const int i = warp;
    const float di = g_dis[i];
    const int f = lane * 4;
    float4 acc = make_float4(0.f, 0.f, 0.f, 0.f);
    gather_fma(acc, &g_t[(size_t)i * HDIM], f, di * di);   // self loop
    int s0 = g_off[i], s1 = g_off[i + 1];
    s0 = min(max(s0, 0), EMAX); s1 = min(max(s1, s0), EMAX);
    for (int j = s0; j < s1; j++) {
        int s = g_srcs[j];
        s = min(max(s, 0), n - 1);
        gather_fma(acc, &g_t[(size_t)s * HDIM], f, g_dis[s] * di);
    }
    float4 bb = *(const float4*)&b1[f];
    acc.x = fmaxf(acc.x + bb.x, 0.f);
    acc.y = fmaxf(acc.y + bb.y, 0.f);
    acc.z = fmaxf(acc.z + bb.z, 0.f);
    acc.w = fmaxf(acc.w + bb.w, 0.f);
    uint2 packed;
    *(__half2*)&packed.x = __floats2half2_rn(acc.x, acc.y);
    *(__half2*)&packed.y = __floats2half2_rn(acc.z, acc.w);
    *(uint2*)&g_h1[(size_t)i * HDIM + f] = packed;
}

__global__ void agg2_kernel(const float* __restrict__ bmu,
                            const float* __restrict__ bvar,
                            float* __restrict__ out, int n) {
    int warp = (blockIdx.x * blockDim.x + threadIdx.x) >> 5;
    int lane = threadIdx.x & 31;
    if (warp >= n) return;
    const int i = warp;
    const float di = g_dis[i];
    const int f = lane * 4;
    float4 acc = make_float4(0.f, 0.f, 0.f, 0.f);
    gather_fma(acc, &g_t[(size_t)i * HDIM], f, di * di);   // self loop
    int s0 = g_off[i], s1 = g_off[i + 1];
    s0 = min(max(s0, 0), EMAX); s1 = min(max(s1, s0), EMAX);
    for (int j = s0; j < s1; j++) {
        int s = g_srcs[j];
        s = min(max(s, 0), n - 1);
        gather_fma(acc, &g_t[(size_t)s * HDIM], f, g_dis[s] * di);
    }
    // split: cols [0,64) -> mu (+bmu), [64,128) -> sigma (+bvar)
    if (f < DDIM) {
        float4 bb = *(const float4*)&bmu[f];
        acc.x += bb.x; acc.y += bb.y; acc.z += bb.z; acc.w += bb.w;
        *(float4*)&out[(size_t)i * DDIM + f] = acc;
    } else {
        int fv = f - DDIM;
        float4 bb = *(const float4*)&bvar[fv];
        acc.x += bb.x; acc.y += bb.y; acc.z += bb.z; acc.w += bb.w;
        *(float4*)&out[(size_t)n * DDIM + (size_t)i * DDIM + fv] = acc;
    }
}

// ---------------- launch ----------------
static cudaStream_t g_s2 = nullptr;
static cudaEvent_t  g_evF = nullptr;
static cudaEvent_t  g_evJ = nullptr;
static int          g_streams_ok = -1;   // -1 = uninitialized

extern "C" void kernel_launch(void* const* d_in, const int* in_sizes, int n_in,
                              void* d_out, int out_size) {
    const float* x    = (const float*)d_in[0];
    const void*  ei   = d_in[1];
    const float* W1   = (const float*)d_in[2];
    const float* b1   = (const float*)d_in[3];
    const float* Wmu  = (const float*)d_in[4];
    const float* bmu  = (const float*)d_in[5];
    const float* Wvar = (const float*)d_in[6];
    const float* bvar = (const float*)d_in[7];
    float* out = (float*)d_out;

    const int n = in_sizes[0] / FDIM;     // 100000
    const int e = in_sizes[1] / 2;        // 1600000
    const int nb = (n + 255) / 256;       // 391

    if (g_streams_ok < 0) {
        g_streams_ok = 1;
        if (cudaStreamCreateWithFlags(&g_s2, cudaStreamNonBlocking) != cudaSuccess) g_streams_ok = 0;
        if (g_streams_ok && cudaEventCreateWithFlags(&g_evF, cudaEventDisableTiming) != cudaSuccess) g_streams_ok = 0;
        if (g_streams_ok && cudaEventCreateWithFlags(&g_evJ, cudaEventDisableTiming) != cudaSuccess) g_streams_ok = 0;
    }
    const bool fork = (g_streams_ok == 1);
    cudaStream_t s2 = fork ? g_s2 : (cudaStream_t)0;

    if (fork) {
        cudaEventRecord(g_evF, 0);
        cudaStreamWaitEvent(s2, g_evF, 0);
    }

    // CSR head on origin stream
    zeros_kernel<<<(n + 255) / 256, 256>>>(n);
    detect_kernel<<<8, 256>>>(ei, e, n);
    count_kernel<<<(e + 255) / 256, 256>>>(ei, e, n);

    // GEMM1 on worker stream — overlaps the CSR build
    gemm128_kernel<<<(n + TBM - 1) / TBM, 256, 0, s2>>>(x, W1, n, FDIM, 0);
    if (fork) cudaEventRecord(g_evJ, s2);

    // CSR tail on origin stream
    dis_kernel<<<(n + 255) / 256, 256>>>(n);
    block_scan_kernel<<<nb, 256>>>(n);
    bsum_scan_kernel<<<1, 512>>>(nb);
    add_off_kernel<<<(n + 255) / 256, 256>>>(n, e);
    fill_kernel<<<(e + 255) / 256, 256>>>(ei, e, n);
    wcat_kernel<<<(HDIM * HDIM + 255) / 256, 256>>>(Wmu, Wvar);

    if (fork) cudaStreamWaitEvent((cudaStream_t)0, g_evJ, 0);

    // Layer 1 aggregate: h1 = relu(agg(t) + b1) -> fp16
    agg1_kernel<<<(n + 7) / 8, 256>>>(b1, n);

    // Layers 2+3 fused: t = h1 @ [Wmu|Wvar] ; out = agg(t) + [bmu|bvar]
    gemm128_kernel<<<(n + TBM - 1) / TBM, 256>>>(x, W1, n, HDIM, 1);
    agg2_kernel<<<(n + 7) / 8, 256>>>(bmu, bvar, out, n);
}